// round 2
// baseline (speedup 1.0000x reference)
#include <cuda_runtime.h>
#include <cuda_bf16.h>
#include <cstdint>

// ---------------------------------------------------------------------------
// GCN: 4 layers, N=10000 nodes, E=160000 edges (+N self loops), C=512 (Cin=256)
//   per layer: h = relu( Anorm @ (x W) + b )   (last layer: no relu)
// Plan:
//   1) build deg (counted on col, incl self loops), dinv = rsqrt(deg)
//   2) build CSR sorted by destination col: ptr/src/w  (w = dinv[row]*dinv[col])
//   3) per layer: tf32 tensor-core GEMM  ->  CSR SpMM (+bias, relu)
// NOTE: harness delivers int64 inputs as int32 -> edge_index is const int*.
// ---------------------------------------------------------------------------

#define NMAX     10016
#define EMAX     200032
#define CDIM     512

__device__ float g_buf[2][NMAX * CDIM];   // ping-pong feature buffers
__device__ int   g_src[EMAX];
__device__ float g_w[EMAX];
__device__ int   g_ptr[NMAX + 1];
__device__ int   g_deg[NMAX];
__device__ int   g_cur[NMAX];
__device__ float g_dinv[NMAX];

__device__ __forceinline__ int clampi(int v, int n) {
    return v < 0 ? 0 : (v >= n ? n - 1 : v);
}

// ---------------------------- preprocessing --------------------------------

__global__ void init_kernel(int n) {
    int i = blockIdx.x * blockDim.x + threadIdx.x;
    if (i < n) { g_deg[i] = 1; g_cur[i] = 0; }   // self loop counted up front
}

__global__ void count_kernel(const int* __restrict__ ei, int E, int n) {
    int e = blockIdx.x * blockDim.x + threadIdx.x;
    if (e < E) atomicAdd(&g_deg[clampi(ei[E + e], n)], 1);
}

__global__ void dinv_kernel(int n) {
    int i = blockIdx.x * blockDim.x + threadIdx.x;
    if (i < n) g_dinv[i] = rsqrtf((float)g_deg[i]);
}

// single-block exclusive scan of g_deg -> g_ptr  (n up to NMAX)
__global__ void scan_kernel(int n) {
    __shared__ int s[1024];
    __shared__ int carry;
    int tid = threadIdx.x;
    if (tid == 0) carry = 0;
    __syncthreads();
    for (int base = 0; base < n; base += 1024) {
        int idx = base + tid;
        int v = (idx < n) ? g_deg[idx] : 0;
        s[tid] = v;
        __syncthreads();
        int x = v;
        #pragma unroll
        for (int off = 1; off < 1024; off <<= 1) {
            int y = (tid >= off) ? s[tid - off] : 0;
            __syncthreads();
            x += y;
            s[tid] = x;
            __syncthreads();
        }
        if (idx < n) g_ptr[idx] = carry + x - v;   // exclusive
        __syncthreads();                            // all reads of carry done
        if (tid == 1023) carry += s[1023];
        __syncthreads();
    }
    if (tid == 0) g_ptr[n] = carry;
}

__global__ void fill_kernel(const int* __restrict__ ei, int E, int n) {
    int e = blockIdx.x * blockDim.x + threadIdx.x;
    if (e >= E + n) return;
    int r, c;
    if (e < E) { r = clampi(ei[e], n); c = clampi(ei[E + e], n); }
    else       { r = c = e - E; }                    // self loop
    int pos = g_ptr[c] + atomicAdd(&g_cur[c], 1);
    if (pos < EMAX) {
        g_src[pos] = r;
        g_w[pos]   = g_dinv[r] * g_dinv[c];
    }
}

// ------------------------------- tf32 GEMM ---------------------------------
// C[M x 512] = A[M x K] @ W[K x 512]
// Block tile 128x128, BK=16, 256 threads (8 warps as 4x2), warp tile 32x64,
// mma.sync m16n8k8 tf32. Double-buffered smem, K-major smem for frag loads.

__device__ __forceinline__ float to_tf32(float x) {
    unsigned u;
    asm("cvt.rna.tf32.f32 %0, %1;" : "=r"(u) : "f"(x));
    return __uint_as_float(u);
}

__device__ __forceinline__ void mma_tf32(float* c, const float* a, const float* b) {
    asm volatile(
        "mma.sync.aligned.m16n8k8.row.col.f32.tf32.tf32.f32 "
        "{%0,%1,%2,%3}, {%4,%5,%6,%7}, {%8,%9}, {%0,%1,%2,%3};"
        : "+f"(c[0]), "+f"(c[1]), "+f"(c[2]), "+f"(c[3])
        : "r"(__float_as_uint(a[0])), "r"(__float_as_uint(a[1])),
          "r"(__float_as_uint(a[2])), "r"(__float_as_uint(a[3])),
          "r"(__float_as_uint(b[0])), "r"(__float_as_uint(b[1])));
}

#define SMS 136   // smem row stride (128 + 8): conflict-free frag loads

__global__ __launch_bounds__(256, 2)
void gemm_tf32(const float* __restrict__ Xin, const float* __restrict__ W,
               int M, int K, int insel, int outsel)
{
    const float* A = (insel < 0) ? Xin : g_buf[insel];
    float* C = g_buf[outsel];
    const int N = CDIM;

    __shared__ __align__(16) float As[2][16][SMS];  // [k][m]
    __shared__ __align__(16) float Bs[2][16][SMS];  // [k][n]

    int tid  = threadIdx.x;
    int bm   = blockIdx.x * 128;
    int bn   = blockIdx.y * 128;
    int wid  = tid >> 5, lane = tid & 31;
    int wm   = (wid >> 1) * 32;
    int wn   = (wid & 1) * 64;
    int tg   = lane & 3, gp = lane >> 2;

    float acc[2][8][4];
    #pragma unroll
    for (int mt = 0; mt < 2; mt++)
        #pragma unroll
        for (int nt = 0; nt < 8; nt++)
            #pragma unroll
            for (int q = 0; q < 4; q++) acc[mt][nt][q] = 0.f;

    // A load map: 2 float4/thread: row = tid>>2 (+64), cols (tid&3)*4..+3
    int a_row0 = (tid >> 2), a_row1 = a_row0 + 64;
    int a_c4   = (tid & 3) * 4;
    // B load map: 2 float4/thread: row = tid>>5 (+8), cols (tid&31)*4..+3
    int b_row0 = (tid >> 5), b_row1 = b_row0 + 8;
    int b_c    = (tid & 31) * 4;

    const float4 z4 = make_float4(0.f, 0.f, 0.f, 0.f);
    int ktiles = K >> 4;

    float4 av0, av1, bv0, bv1;

    auto loadG = [&](int kt) {
        int k0 = kt << 4;
        int r0 = bm + a_row0, r1 = bm + a_row1;
        av0 = (r0 < M) ? *(const float4*)&A[r0 * K + k0 + a_c4] : z4;
        av1 = (r1 < M) ? *(const float4*)&A[r1 * K + k0 + a_c4] : z4;
        bv0 = *(const float4*)&W[(k0 + b_row0) * N + bn + b_c];
        bv1 = *(const float4*)&W[(k0 + b_row1) * N + bn + b_c];
    };
    auto storeS = [&](int buf) {
        As[buf][a_c4 + 0][a_row0] = to_tf32(av0.x);
        As[buf][a_c4 + 1][a_row0] = to_tf32(av0.y);
        As[buf][a_c4 + 2][a_row0] = to_tf32(av0.z);
        As[buf][a_c4 + 3][a_row0] = to_tf32(av0.w);
        As[buf][a_c4 + 0][a_row1] = to_tf32(av1.x);
        As[buf][a_c4 + 1][a_row1] = to_tf32(av1.y);
        As[buf][a_c4 + 2][a_row1] = to_tf32(av1.z);
        As[buf][a_c4 + 3][a_row1] = to_tf32(av1.w);
        float4 t0 = make_float4(to_tf32(bv0.x), to_tf32(bv0.y), to_tf32(bv0.z), to_tf32(bv0.w));
        float4 t1 = make_float4(to_tf32(bv1.x), to_tf32(bv1.y), to_tf32(bv1.z), to_tf32(bv1.w));
        *(float4*)&Bs[buf][b_row0][b_c] = t0;
        *(float4*)&Bs[buf][b_row1][b_c] = t1;
    };
    auto compute = [&](int buf) {
        #pragma unroll
        for (int kk = 0; kk < 16; kk += 8) {
            float a[2][4], b[8][2];
            #pragma unroll
            for (int mt = 0; mt < 2; mt++) {
                int r = wm + mt * 16 + gp;
                a[mt][0] = As[buf][kk + tg][r];
                a[mt][1] = As[buf][kk + tg][r + 8];
                a[mt][2] = As[buf][kk + tg + 4][r];
                a[mt][3] = As[buf][kk + tg + 4][r + 8];
            }
            #pragma unroll
            for (int nt = 0; nt < 8; nt++) {
                int c = wn + nt * 8 + gp;
                b[nt][0] = Bs[buf][kk + tg][c];
                b[nt][1] = Bs[buf][kk + tg + 4][c];
            }
            #pragma unroll
            for (int mt = 0; mt < 2; mt++)
                #pragma unroll
                for (int nt = 0; nt < 8; nt++)
                    mma_tf32(acc[mt][nt], a[mt], b[nt]);
        }
    };

    loadG(0);
    storeS(0);
    __syncthreads();

    for (int kt = 0; kt < ktiles; kt++) {
        int buf = kt & 1;
        if (kt + 1 < ktiles) loadG(kt + 1);
        compute(buf);
        if (kt + 1 < ktiles) {
            storeS(buf ^ 1);
            __syncthreads();
        }
    }

    // epilogue
    #pragma unroll
    for (int mt = 0; mt < 2; mt++) {
        #pragma unroll
        for (int nt = 0; nt < 8; nt++) {
            int r = bm + wm + mt * 16 + gp;
            int c = bn + wn + nt * 8 + tg * 2;
            if (r < M)
                *(float2*)&C[r * N + c] = make_float2(acc[mt][nt][0], acc[mt][nt][1]);
            if (r + 8 < M)
                *(float2*)&C[(r + 8) * N + c] = make_float2(acc[mt][nt][2], acc[mt][nt][3]);
        }
    }
}

// ------------------------------- CSR SpMM ----------------------------------
// one block per destination node, 128 threads x float4 = 512 channels
__global__ __launch_bounds__(128)
void spmm_kernel(const float* __restrict__ bias, float* __restrict__ dout,
                 int insel, int outsel, int relu)
{
    int v = blockIdx.x;
    int t = threadIdx.x;
    const float4* H = (const float4*)g_buf[insel];
    float4* O = (outsel < 0) ? (float4*)dout : (float4*)g_buf[outsel];

    int beg = g_ptr[v], end = g_ptr[v + 1];
    float4 acc = make_float4(0.f, 0.f, 0.f, 0.f);

    int e = beg;
    for (; e + 1 < end; e += 2) {
        int   s0 = g_src[e],     s1 = g_src[e + 1];
        float w0 = g_w[e],       w1 = g_w[e + 1];
        float4 h0 = H[s0 * 128 + t];
        float4 h1 = H[s1 * 128 + t];
        acc.x += w0 * h0.x + w1 * h1.x;
        acc.y += w0 * h0.y + w1 * h1.y;
        acc.z += w0 * h0.z + w1 * h1.z;
        acc.w += w0 * h0.w + w1 * h1.w;
    }
    if (e < end) {
        int s0 = g_src[e];
        float w0 = g_w[e];
        float4 h0 = H[s0 * 128 + t];
        acc.x += w0 * h0.x; acc.y += w0 * h0.y;
        acc.z += w0 * h0.z; acc.w += w0 * h0.w;
    }

    float4 bb = ((const float4*)bias)[t];
    acc.x += bb.x; acc.y += bb.y; acc.z += bb.z; acc.w += bb.w;
    if (relu) {
        acc.x = fmaxf(acc.x, 0.f); acc.y = fmaxf(acc.y, 0.f);
        acc.z = fmaxf(acc.z, 0.f); acc.w = fmaxf(acc.w, 0.f);
    }
    O[v * 128 + t] = acc;
}

// ------------------------------- driver ------------------------------------

extern "C" void kernel_launch(void* const* d_in, const int* in_sizes, int n_in,
                              void* d_out, int out_size)
{
    const float* x  = (const float*)d_in[0];
    const int*   ei = (const int*)d_in[1];      // int64 downcast to int32 by harness
    const float* W1 = (const float*)d_in[2];
    const float* b1 = (const float*)d_in[3];
    const float* W2 = (const float*)d_in[4];
    const float* b2 = (const float*)d_in[5];
    const float* W3 = (const float*)d_in[6];
    const float* b3 = (const float*)d_in[7];
    const float* W4 = (const float*)d_in[8];
    const float* b4 = (const float*)d_in[9];
    float* out = (float*)d_out;

    int Cin = in_sizes[2] / CDIM;         // 256
    int N   = in_sizes[0] / Cin;          // 10000
    int E   = in_sizes[1] / 2;            // 160000

    // ---- graph preprocessing ----
    int nb = (N + 255) / 256;
    init_kernel<<<nb, 256>>>(N);
    count_kernel<<<(E + 255) / 256, 256>>>(ei, E, N);
    dinv_kernel<<<nb, 256>>>(N);
    scan_kernel<<<1, 1024>>>(N);
    fill_kernel<<<(E + N + 255) / 256, 256>>>(ei, E, N);

    dim3 ggrid((N + 127) / 128, CDIM / 128);

    // layer 1: x @ W1 -> buf0 ; aggregate -> buf1 (+b1, relu)
    gemm_tf32<<<ggrid, 256>>>(x, W1, N, Cin, -1, 0);
    spmm_kernel<<<N, 128>>>(b1, nullptr, 0, 1, 1);
    // layer 2
    gemm_tf32<<<ggrid, 256>>>(nullptr, W2, N, CDIM, 1, 0);
    spmm_kernel<<<N, 128>>>(b2, nullptr, 0, 1, 1);
    // layer 3
    gemm_tf32<<<ggrid, 256>>>(nullptr, W3, N, CDIM, 1, 0);
    spmm_kernel<<<N, 128>>>(b3, nullptr, 0, 1, 1);
    // layer 4 (no relu, write d_out)
    gemm_tf32<<<ggrid, 256>>>(nullptr, W4, N, CDIM, 1, 0);
    spmm_kernel<<<N, 128>>>(b4, out, 0, -1, 0);
}

// round 3
// speedup vs baseline: 1.0694x; 1.0694x over previous
#include <cuda_runtime.h>
#include <cuda_bf16.h>
#include <cstdint>

// ---------------------------------------------------------------------------
// GCN: 4 layers, N=10000 nodes, E=160000 edges (+N self loops), C=512 (Cin=256)
//   per layer: h = relu( Anorm @ (x W) + b )   (last layer: no relu)
//   1) deg (counted on col, incl self loops), dinv = rsqrt(deg)
//   2) CSR sorted by destination: ptr/src/w  (w = dinv[row]*dinv[col])
//   3) per layer: tf32 tensor-core GEMM  ->  CSR SpMM (+bias, relu)
// edge_index arrives as int32 [2, E] (harness downcasts int64).
// ---------------------------------------------------------------------------

#define NMAX     10016
#define EMAX     200032
#define CDIM     512

__device__ float g_buf[2][NMAX * CDIM];   // ping-pong feature buffers
__device__ int   g_src[EMAX];
__device__ float g_w[EMAX];
__device__ int   g_ptr[NMAX + 1];
__device__ int   g_deg[NMAX];
__device__ int   g_cur[NMAX];
__device__ float g_dinv[NMAX];

__device__ __forceinline__ int clampi(int v, int n) {
    return v < 0 ? 0 : (v >= n ? n - 1 : v);
}

// ---------------------------- preprocessing --------------------------------

__global__ void init_kernel(int n) {
    int i = blockIdx.x * blockDim.x + threadIdx.x;
    if (i < n) { g_deg[i] = 1; g_cur[i] = 0; }   // self loop counted up front
}

__global__ void count_kernel(const int* __restrict__ ei, int E, int n) {
    int e = blockIdx.x * blockDim.x + threadIdx.x;
    if (e < E) atomicAdd(&g_deg[clampi(ei[E + e], n)], 1);
}

// fused fast exclusive scan (g_deg -> g_ptr) + dinv, one block of 1024.
// each thread serially accumulates `per` elements, then warp-shuffle block scan.
__global__ void scan_dinv_kernel(int n) {
    __shared__ int warp_tot[32];
    int tid  = threadIdx.x;
    int lane = tid & 31, wid = tid >> 5;
    int per  = (n + 1023) >> 10;        // 10 for n=10000
    int beg  = tid * per;
    int end  = min(beg + per, n);

    int local[12];                       // per <= 12 assumed (n <= 12288)
    int t = 0;
    for (int i = beg; i < end; i++) {
        int d = g_deg[i];
        local[i - beg] = t;
        t += d;
        g_dinv[i] = rsqrtf((float)d);
    }

    // warp inclusive scan of per-thread totals
    int x = t;
    #pragma unroll
    for (int off = 1; off < 32; off <<= 1) {
        int y = __shfl_up_sync(0xffffffffu, x, off);
        if (lane >= off) x += y;
    }
    if (lane == 31) warp_tot[wid] = x;
    __syncthreads();
    if (wid == 0) {
        int v = warp_tot[lane];
        #pragma unroll
        for (int off = 1; off < 32; off <<= 1) {
            int y = __shfl_up_sync(0xffffffffu, v, off);
            if (lane >= off) v += y;
        }
        warp_tot[lane] = v;              // inclusive warp totals
    }
    __syncthreads();

    int warp_off = (wid > 0) ? warp_tot[wid - 1] : 0;
    int excl = warp_off + x - t;         // exclusive prefix of this thread
    for (int i = beg; i < end; i++) g_ptr[i] = excl + local[i - beg];
    if (tid == 0) g_ptr[n] = warp_tot[31];
}

__global__ void fill_kernel(const int* __restrict__ ei, int E, int n) {
    int e = blockIdx.x * blockDim.x + threadIdx.x;
    if (e >= E + n) return;
    int r, c;
    if (e < E) { r = clampi(ei[e], n); c = clampi(ei[E + e], n); }
    else       { r = c = e - E; }                    // self loop
    int pos = g_ptr[c] + atomicAdd(&g_cur[c], 1);
    if (pos < EMAX) {
        g_src[pos] = r;
        g_w[pos]   = g_dinv[r] * g_dinv[c];
    }
}

// ------------------------------- tf32 GEMM ---------------------------------
// C[M x 512] = A[M x K] @ W[K x 512]
// Block tile 64x128, BK=16, 128 threads (4 warps as 2x2), warp tile 32x64,
// mma.sync m16n8k8 tf32, double-buffered smem. Smaller tiles -> 628 tiles,
// occ 3-4 -> better wave balance than 128x128 (316 tiles / 296 slots).

__device__ __forceinline__ float to_tf32(float x) {
    unsigned u;
    asm("cvt.rna.tf32.f32 %0, %1;" : "=r"(u) : "f"(x));
    return __uint_as_float(u);
}

__device__ __forceinline__ void mma_tf32(float* c, const float* a, const float* b) {
    asm volatile(
        "mma.sync.aligned.m16n8k8.row.col.f32.tf32.tf32.f32 "
        "{%0,%1,%2,%3}, {%4,%5,%6,%7}, {%8,%9}, {%0,%1,%2,%3};"
        : "+f"(c[0]), "+f"(c[1]), "+f"(c[2]), "+f"(c[3])
        : "r"(__float_as_uint(a[0])), "r"(__float_as_uint(a[1])),
          "r"(__float_as_uint(a[2])), "r"(__float_as_uint(a[3])),
          "r"(__float_as_uint(b[0])), "r"(__float_as_uint(b[1])));
}

#define SMSA 72    // As row stride (64 + 8)
#define SMSB 136   // Bs row stride (128 + 8)

__global__ __launch_bounds__(128)
void gemm_tf32(const float* __restrict__ Xin, const float* __restrict__ W,
               int M, int K, int insel, int outsel)
{
    const float* A = (insel < 0) ? Xin : g_buf[insel];
    float* C = g_buf[outsel];
    const int N = CDIM;

    __shared__ __align__(16) float As[2][16][SMSA];  // [k][m]
    __shared__ __align__(16) float Bs[2][16][SMSB];  // [k][n]

    int tid  = threadIdx.x;
    int bm   = blockIdx.x * 64;
    int bn   = blockIdx.y * 128;
    int wid  = tid >> 5, lane = tid & 31;
    int wm   = (wid >> 1) * 32;
    int wn   = (wid & 1) * 64;
    int tg   = lane & 3, gp = lane >> 2;

    float acc[2][8][4];
    #pragma unroll
    for (int mt = 0; mt < 2; mt++)
        #pragma unroll
        for (int nt = 0; nt < 8; nt++)
            #pragma unroll
            for (int q = 0; q < 4; q++) acc[mt][nt][q] = 0.f;

    // A tile 64x16: 2 float4/thread: rows tid>>2 (+32), cols (tid&3)*4
    int a_row0 = (tid >> 2), a_row1 = a_row0 + 32;
    int a_c4   = (tid & 3) * 4;
    // B tile 16x128: 4 float4/thread: rows tid>>5 (+4,+8,+12), cols (tid&31)*4
    int b_row  = (tid >> 5);
    int b_c    = (tid & 31) * 4;

    const float4 z4 = make_float4(0.f, 0.f, 0.f, 0.f);
    int ktiles = K >> 4;

    float4 av0, av1, bv0, bv1, bv2, bv3;

    auto loadG = [&](int kt) {
        int k0 = kt << 4;
        int r0 = bm + a_row0, r1 = bm + a_row1;
        av0 = (r0 < M) ? *(const float4*)&A[r0 * K + k0 + a_c4] : z4;
        av1 = (r1 < M) ? *(const float4*)&A[r1 * K + k0 + a_c4] : z4;
        const float* wp = &W[(k0 + b_row) * N + bn + b_c];
        bv0 = *(const float4*)(wp);
        bv1 = *(const float4*)(wp + 4 * N);
        bv2 = *(const float4*)(wp + 8 * N);
        bv3 = *(const float4*)(wp + 12 * N);
    };
    auto storeS = [&](int buf) {
        As[buf][a_c4 + 0][a_row0] = to_tf32(av0.x);
        As[buf][a_c4 + 1][a_row0] = to_tf32(av0.y);
        As[buf][a_c4 + 2][a_row0] = to_tf32(av0.z);
        As[buf][a_c4 + 3][a_row0] = to_tf32(av0.w);
        As[buf][a_c4 + 0][a_row1] = to_tf32(av1.x);
        As[buf][a_c4 + 1][a_row1] = to_tf32(av1.y);
        As[buf][a_c4 + 2][a_row1] = to_tf32(av1.z);
        As[buf][a_c4 + 3][a_row1] = to_tf32(av1.w);
        float4 t0 = make_float4(to_tf32(bv0.x), to_tf32(bv0.y), to_tf32(bv0.z), to_tf32(bv0.w));
        float4 t1 = make_float4(to_tf32(bv1.x), to_tf32(bv1.y), to_tf32(bv1.z), to_tf32(bv1.w));
        float4 t2 = make_float4(to_tf32(bv2.x), to_tf32(bv2.y), to_tf32(bv2.z), to_tf32(bv2.w));
        float4 t3 = make_float4(to_tf32(bv3.x), to_tf32(bv3.y), to_tf32(bv3.z), to_tf32(bv3.w));
        *(float4*)&Bs[buf][b_row     ][b_c] = t0;
        *(float4*)&Bs[buf][b_row +  4][b_c] = t1;
        *(float4*)&Bs[buf][b_row +  8][b_c] = t2;
        *(float4*)&Bs[buf][b_row + 12][b_c] = t3;
    };
    auto compute = [&](int buf) {
        #pragma unroll
        for (int kk = 0; kk < 16; kk += 8) {
            float a[2][4], b[8][2];
            #pragma unroll
            for (int mt = 0; mt < 2; mt++) {
                int r = wm + mt * 16 + gp;
                a[mt][0] = As[buf][kk + tg][r];
                a[mt][1] = As[buf][kk + tg][r + 8];
                a[mt][2] = As[buf][kk + tg + 4][r];
                a[mt][3] = As[buf][kk + tg + 4][r + 8];
            }
            #pragma unroll
            for (int nt = 0; nt < 8; nt++) {
                int c = wn + nt * 8 + gp;
                b[nt][0] = Bs[buf][kk + tg][c];
                b[nt][1] = Bs[buf][kk + tg + 4][c];
            }
            #pragma unroll
            for (int mt = 0; mt < 2; mt++)
                #pragma unroll
                for (int nt = 0; nt < 8; nt++)
                    mma_tf32(acc[mt][nt], a[mt], b[nt]);
        }
    };

    loadG(0);
    storeS(0);
    __syncthreads();

    for (int kt = 0; kt < ktiles; kt++) {
        int buf = kt & 1;
        if (kt + 1 < ktiles) loadG(kt + 1);
        compute(buf);
        if (kt + 1 < ktiles) {
            storeS(buf ^ 1);
            __syncthreads();
        }
    }

    // epilogue
    #pragma unroll
    for (int mt = 0; mt < 2; mt++) {
        #pragma unroll
        for (int nt = 0; nt < 8; nt++) {
            int r = bm + wm + mt * 16 + gp;
            int c = bn + wn + nt * 8 + tg * 2;
            if (r < M)
                *(float2*)&C[r * N + c] = make_float2(acc[mt][nt][0], acc[mt][nt][1]);
            if (r + 8 < M)
                *(float2*)&C[(r + 8) * N + c] = make_float2(acc[mt][nt][2], acc[mt][nt][3]);
        }
    }
}

// ------------------------------- CSR SpMM ----------------------------------
// one block per destination node, 128 threads x float4 = 512 channels
__global__ __launch_bounds__(128)
void spmm_kernel(const float* __restrict__ bias, float* __restrict__ dout,
                 int insel, int outsel, int relu)
{
    int v = blockIdx.x;
    int t = threadIdx.x;
    const float4* H = (const float4*)g_buf[insel];
    float4* O = (outsel < 0) ? (float4*)dout : (float4*)g_buf[outsel];

    int beg = g_ptr[v], end = g_ptr[v + 1];
    float4 acc = make_float4(0.f, 0.f, 0.f, 0.f);

    int e = beg;
    for (; e + 1 < end; e += 2) {
        int   s0 = g_src[e],     s1 = g_src[e + 1];
        float w0 = g_w[e],       w1 = g_w[e + 1];
        float4 h0 = H[s0 * 128 + t];
        float4 h1 = H[s1 * 128 + t];
        acc.x += w0 * h0.x + w1 * h1.x;
        acc.y += w0 * h0.y + w1 * h1.y;
        acc.z += w0 * h0.z + w1 * h1.z;
        acc.w += w0 * h0.w + w1 * h1.w;
    }
    if (e < end) {
        int s0 = g_src[e];
        float w0 = g_w[e];
        float4 h0 = H[s0 * 128 + t];
        acc.x += w0 * h0.x; acc.y += w0 * h0.y;
        acc.z += w0 * h0.z; acc.w += w0 * h0.w;
    }

    float4 bb = ((const float4*)bias)[t];
    acc.x += bb.x; acc.y += bb.y; acc.z += bb.z; acc.w += bb.w;
    if (relu) {
        acc.x = fmaxf(acc.x, 0.f); acc.y = fmaxf(acc.y, 0.f);
        acc.z = fmaxf(acc.z, 0.f); acc.w = fmaxf(acc.w, 0.f);
    }
    O[v * 128 + t] = acc;
}

// ------------------------------- driver ------------------------------------

extern "C" void kernel_launch(void* const* d_in, const int* in_sizes, int n_in,
                              void* d_out, int out_size)
{
    const float* x  = (const float*)d_in[0];
    const int*   ei = (const int*)d_in[1];      // int64 downcast to int32 by harness
    const float* W1 = (const float*)d_in[2];
    const float* b1 = (const float*)d_in[3];
    const float* W2 = (const float*)d_in[4];
    const float* b2 = (const float*)d_in[5];
    const float* W3 = (const float*)d_in[6];
    const float* b3 = (const float*)d_in[7];
    const float* W4 = (const float*)d_in[8];
    const float* b4 = (const float*)d_in[9];
    float* out = (float*)d_out;

    int Cin = in_sizes[2] / CDIM;         // 256
    int N   = in_sizes[0] / Cin;          // 10000
    int E   = in_sizes[1] / 2;            // 160000

    // ---- graph preprocessing ----
    init_kernel<<<(N + 255) / 256, 256>>>(N);
    count_kernel<<<(E + 255) / 256, 256>>>(ei, E, N);
    scan_dinv_kernel<<<1, 1024>>>(N);
    fill_kernel<<<(E + N + 255) / 256, 256>>>(ei, E, N);

    dim3 ggrid((N + 63) / 64, CDIM / 128);

    // layer 1: x @ W1 -> buf0 ; aggregate -> buf1 (+b1, relu)
    gemm_tf32<<<ggrid, 128>>>(x, W1, N, Cin, -1, 0);
    spmm_kernel<<<N, 128>>>(b1, nullptr, 0, 1, 1);
    // layer 2
    gemm_tf32<<<ggrid, 128>>>(nullptr, W2, N, CDIM, 1, 0);
    spmm_kernel<<<N, 128>>>(b2, nullptr, 0, 1, 1);
    // layer 3
    gemm_tf32<<<ggrid, 128>>>(nullptr, W3, N, CDIM, 1, 0);
    spmm_kernel<<<N, 128>>>(b3, nullptr, 0, 1, 1);
    // layer 4 (no relu, write d_out)
    gemm_tf32<<<ggrid, 128>>>(nullptr, W4, N, CDIM, 1, 0);
    spmm_kernel<<<N, 128>>>(b4, out, 0, -1, 0);
}

// round 5
// speedup vs baseline: 1.1627x; 1.0872x over previous
#include <cuda_runtime.h>
#include <cuda_bf16.h>
#include <cstdint>

// ---------------------------------------------------------------------------
// GCN, 4 layers, restructured:  h_out = relu( (A @ h) @ W + b )
//   SpMM (pure gather-sum) FIRST, then mma.sync tf32 GEMM with fused bias+relu.
// NOTE: harness builds at sm_103 (no 'a') -> tcgen05 unavailable; legacy
// mma.sync m16n8k8 tf32 with a 3-stage cp.async pipeline instead.
// edge_index arrives as int32 [2, E] (harness downcasts int64).
// ---------------------------------------------------------------------------

#define NMAX     10016
#define EMAX     200032
#define CDIM     512

__device__ float g_buf[2][NMAX * CDIM];   // ping-pong feature buffers
__device__ int   g_src[EMAX];
__device__ float g_w[EMAX];
__device__ int   g_ptr[NMAX + 1];
__device__ int   g_deg[NMAX];
__device__ int   g_cur[NMAX];
__device__ float g_dinv[NMAX];

__device__ __forceinline__ int clampi(int v, int n) {
    return v < 0 ? 0 : (v >= n ? n - 1 : v);
}

__device__ __forceinline__ uint32_t smem_u32(const void* p) {
    uint32_t a;
    asm("{ .reg .u64 t; cvta.to.shared.u64 t, %1; cvt.u32.u64 %0, t; }"
        : "=r"(a) : "l"(p));
    return a;
}

#define CP_ASYNC16(dst, src) \
    asm volatile("cp.async.cg.shared.global [%0], [%1], 16;" \
                 :: "r"(dst), "l"(src) : "memory")
#define CP_COMMIT()  asm volatile("cp.async.commit_group;" ::: "memory")
#define CP_WAIT1()   asm volatile("cp.async.wait_group 1;" ::: "memory")
#define CP_WAIT0()   asm volatile("cp.async.wait_group 0;" ::: "memory")

// ---------------------------- preprocessing --------------------------------

__global__ void init_kernel(int n) {
    int i = blockIdx.x * blockDim.x + threadIdx.x;
    if (i < n) { g_deg[i] = 1; g_cur[i] = 0; }
}

__global__ void count_kernel(const int* __restrict__ ei, int E, int n) {
    int e = blockIdx.x * blockDim.x + threadIdx.x;
    if (e < E) atomicAdd(&g_deg[clampi(ei[E + e], n)], 1);
}

__global__ void scan_dinv_kernel(int n) {
    __shared__ int warp_tot[32];
    int tid  = threadIdx.x;
    int lane = tid & 31, wid = tid >> 5;
    int per  = (n + 1023) >> 10;
    int beg  = tid * per;
    int end  = min(beg + per, n);

    int local[12];
    int t = 0;
    for (int i = beg; i < end; i++) {
        int d = g_deg[i];
        local[i - beg] = t;
        t += d;
        g_dinv[i] = rsqrtf((float)d);
    }
    int x = t;
    #pragma unroll
    for (int off = 1; off < 32; off <<= 1) {
        int y = __shfl_up_sync(0xffffffffu, x, off);
        if (lane >= off) x += y;
    }
    if (lane == 31) warp_tot[wid] = x;
    __syncthreads();
    if (wid == 0) {
        int v = warp_tot[lane];
        #pragma unroll
        for (int off = 1; off < 32; off <<= 1) {
            int y = __shfl_up_sync(0xffffffffu, v, off);
            if (lane >= off) v += y;
        }
        warp_tot[lane] = v;
    }
    __syncthreads();
    int warp_off = (wid > 0) ? warp_tot[wid - 1] : 0;
    int excl = warp_off + x - t;
    for (int i = beg; i < end; i++) g_ptr[i] = excl + local[i - beg];
    if (tid == 0) g_ptr[n] = warp_tot[31];
}

__global__ void fill_kernel(const int* __restrict__ ei, int E, int n) {
    int e = blockIdx.x * blockDim.x + threadIdx.x;
    if (e >= E + n) return;
    int r, c;
    if (e < E) { r = clampi(ei[e], n); c = clampi(ei[E + e], n); }
    else       { r = c = e - E; }
    int pos = g_ptr[c] + atomicAdd(&g_cur[c], 1);
    if (pos < EMAX) {
        g_src[pos] = r;
        g_w[pos]   = g_dinv[r] * g_dinv[c];
    }
}

// ------------------------------- CSR SpMM ----------------------------------
// pure aggregation: dst[v] = sum_e w_e * src[src_e].  blockDim = cols/4.
__global__ void spmm_agg(const float* __restrict__ xin, int srcsel, int dstsel, int c4)
{
    int v = blockIdx.x;
    int t = threadIdx.x;
    const float4* S = (srcsel < 0) ? (const float4*)xin : (const float4*)g_buf[srcsel];
    float4* D = (float4*)g_buf[dstsel];

    int beg = g_ptr[v], end = g_ptr[v + 1];
    float4 acc = make_float4(0.f, 0.f, 0.f, 0.f);

    int e = beg;
    for (; e + 1 < end; e += 2) {
        int   s0 = g_src[e],     s1 = g_src[e + 1];
        float w0 = g_w[e],       w1 = g_w[e + 1];
        float4 h0 = S[s0 * c4 + t];
        float4 h1 = S[s1 * c4 + t];
        acc.x += w0 * h0.x + w1 * h1.x;
        acc.y += w0 * h0.y + w1 * h1.y;
        acc.z += w0 * h0.z + w1 * h1.z;
        acc.w += w0 * h0.w + w1 * h1.w;
    }
    if (e < end) {
        int s0 = g_src[e];
        float w0 = g_w[e];
        float4 h0 = S[s0 * c4 + t];
        acc.x += w0 * h0.x; acc.y += w0 * h0.y;
        acc.z += w0 * h0.z; acc.w += w0 * h0.w;
    }
    D[v * c4 + t] = acc;
}

// ----------------------- tf32 GEMM (cp.async pipeline) ---------------------
// C[M x 512] = A[M x K] @ W[K x 512] (+bias, +relu).
// Block tile 64x128, BK=16, 128 threads (4 warps 2x2), warp tile 32x64.
// 3-stage cp.async.cg pipeline; fp32 in smem, cvt.rna.tf32 at frag load.

__device__ __forceinline__ float to_tf32(float x) {
    unsigned u;
    asm("cvt.rna.tf32.f32 %0, %1;" : "=r"(u) : "f"(x));
    return __uint_as_float(u);
}

__device__ __forceinline__ void mma_tf32(float* c, const float* a, const float* b) {
    asm volatile(
        "mma.sync.aligned.m16n8k8.row.col.f32.tf32.tf32.f32 "
        "{%0,%1,%2,%3}, {%4,%5,%6,%7}, {%8,%9}, {%0,%1,%2,%3};"
        : "+f"(c[0]), "+f"(c[1]), "+f"(c[2]), "+f"(c[3])
        : "r"(__float_as_uint(a[0])), "r"(__float_as_uint(a[1])),
          "r"(__float_as_uint(a[2])), "r"(__float_as_uint(a[3])),
          "r"(__float_as_uint(b[0])), "r"(__float_as_uint(b[1])));
}

#define APAD 20    // As row stride (16 + 4): conflict-free frag loads
#define BPAD 132   // Bs row stride (128 + 4)

__global__ __launch_bounds__(128)
void gemm_tc(const float* __restrict__ W, const float* __restrict__ bias,
             float* __restrict__ dout, int M, int K, int insel, int outsel,
             int relu)
{
    __shared__ __align__(16) float As[3][64][APAD];   // [stage][m][k]
    __shared__ __align__(16) float Bs[3][16][BPAD];   // [stage][k][n]

    const float* A = g_buf[insel];
    float* C = (outsel < 0) ? dout : g_buf[outsel];

    int tid  = threadIdx.x;
    int bm   = blockIdx.x * 64;
    int bn   = blockIdx.y * 128;
    int wid  = tid >> 5, lane = tid & 31;
    int wm   = (wid >> 1) * 32;
    int wn   = (wid & 1) * 64;
    int tg   = lane & 3, gp = lane >> 2;

    float acc[2][8][4];
    #pragma unroll
    for (int mt = 0; mt < 2; mt++)
        #pragma unroll
        for (int nt = 0; nt < 8; nt++)
            #pragma unroll
            for (int q = 0; q < 4; q++) acc[mt][nt][q] = 0.f;

    // A copy map: rows (tid>>2) and (tid>>2)+32, k-cols (tid&3)*4..+3
    int a_row = tid >> 2, a_c = (tid & 3) * 4;
    int gr0 = bm + a_row;      if (gr0 >= M) gr0 = M - 1;
    int gr1 = bm + a_row + 32; if (gr1 >= M) gr1 = M - 1;
    // B copy map: k-rows (tid>>5)+{0,4,8,12}, n-cols (tid&31)*4..+3
    int b_r = tid >> 5, b_c = (tid & 31) * 4;

    uint32_t sa0[3], sa1[3], sb[3][4];
    #pragma unroll
    for (int s = 0; s < 3; s++) {
        sa0[s] = smem_u32(&As[s][a_row][a_c]);
        sa1[s] = smem_u32(&As[s][a_row + 32][a_c]);
        #pragma unroll
        for (int i = 0; i < 4; i++)
            sb[s][i] = smem_u32(&Bs[s][b_r + i * 4][b_c]);
    }

    int ktiles = K >> 4;

    auto prefetch = [&](int kt) {
        int s  = kt % 3;
        int k0 = kt << 4;
        CP_ASYNC16(sa0[s], &A[(size_t)gr0 * K + k0 + a_c]);
        CP_ASYNC16(sa1[s], &A[(size_t)gr1 * K + k0 + a_c]);
        #pragma unroll
        for (int i = 0; i < 4; i++)
            CP_ASYNC16(sb[s][i], &W[(size_t)(k0 + b_r + i * 4) * CDIM + bn + b_c]);
        CP_COMMIT();
    };

    prefetch(0);
    if (ktiles > 1) prefetch(1); else CP_COMMIT();

    for (int kt = 0; kt < ktiles; kt++) {
        if (kt + 1 < ktiles) CP_WAIT1(); else CP_WAIT0();
        __syncthreads();

        int buf = kt % 3;
        #pragma unroll
        for (int kk = 0; kk < 16; kk += 8) {
            float a[2][4], b[8][2];
            #pragma unroll
            for (int mt = 0; mt < 2; mt++) {
                int r = wm + mt * 16 + gp;
                a[mt][0] = to_tf32(As[buf][r    ][kk + tg]);
                a[mt][1] = to_tf32(As[buf][r + 8][kk + tg]);
                a[mt][2] = to_tf32(As[buf][r    ][kk + tg + 4]);
                a[mt][3] = to_tf32(As[buf][r + 8][kk + tg + 4]);
            }
            #pragma unroll
            for (int nt = 0; nt < 8; nt++) {
                int c = wn + nt * 8 + gp;
                b[nt][0] = to_tf32(Bs[buf][kk + tg    ][c]);
                b[nt][1] = to_tf32(Bs[buf][kk + tg + 4][c]);
            }
            #pragma unroll
            for (int mt = 0; mt < 2; mt++)
                #pragma unroll
                for (int nt = 0; nt < 8; nt++)
                    mma_tf32(acc[mt][nt], a[mt], b[nt]);
        }

        if (kt + 2 < ktiles) prefetch(kt + 2);
    }

    // epilogue: + bias, optional relu
    #pragma unroll
    for (int mt = 0; mt < 2; mt++) {
        #pragma unroll
        for (int nt = 0; nt < 8; nt++) {
            int r = bm + wm + mt * 16 + gp;
            int c = bn + wn + nt * 8 + tg * 2;
            float bb0 = __ldg(&bias[c]), bb1 = __ldg(&bias[c + 1]);
            float v0 = acc[mt][nt][0] + bb0, v1 = acc[mt][nt][1] + bb1;
            float v2 = acc[mt][nt][2] + bb0, v3 = acc[mt][nt][3] + bb1;
            if (relu) {
                v0 = fmaxf(v0, 0.f); v1 = fmaxf(v1, 0.f);
                v2 = fmaxf(v2, 0.f); v3 = fmaxf(v3, 0.f);
            }
            if (r < M)     *(float2*)&C[(size_t)r * CDIM + c]       = make_float2(v0, v1);
            if (r + 8 < M) *(float2*)&C[(size_t)(r + 8) * CDIM + c] = make_float2(v2, v3);
        }
    }
}

// ------------------------------- driver ------------------------------------

extern "C" void kernel_launch(void* const* d_in, const int* in_sizes, int n_in,
                              void* d_out, int out_size)
{
    const float* x  = (const float*)d_in[0];
    const int*   ei = (const int*)d_in[1];      // int64 downcast to int32
    const float* W1 = (const float*)d_in[2];
    const float* b1 = (const float*)d_in[3];
    const float* W2 = (const float*)d_in[4];
    const float* b2 = (const float*)d_in[5];
    const float* W3 = (const float*)d_in[6];
    const float* b3 = (const float*)d_in[7];
    const float* W4 = (const float*)d_in[8];
    const float* b4 = (const float*)d_in[9];
    float* out = (float*)d_out;

    int Cin = in_sizes[2] / CDIM;         // 256
    int N   = in_sizes[0] / Cin;          // 10000
    int E   = in_sizes[1] / 2;            // 160000

    // graph preprocessing
    init_kernel<<<(N + 255) / 256, 256>>>(N);
    count_kernel<<<(E + 255) / 256, 256>>>(ei, E, N);
    scan_dinv_kernel<<<1, 1024>>>(N);
    fill_kernel<<<(E + N + 255) / 256, 256>>>(ei, E, N);

    dim3 ggrid((N + 63) / 64, CDIM / 128);   // (157, 4)

    // layer 1: aggregate x (256 cols) -> buf1 ; gemm K=256 (+b1, relu) -> buf0
    spmm_agg<<<N, 64>>>(x, -1, 1, 64);
    gemm_tc<<<ggrid, 128>>>(W1, b1, nullptr, N, Cin, 1, 0, 1);
    // layer 2
    spmm_agg<<<N, 128>>>(nullptr, 0, 1, 128);
    gemm_tc<<<ggrid, 128>>>(W2, b2, nullptr, N, CDIM, 1, 0, 1);
    // layer 3
    spmm_agg<<<N, 128>>>(nullptr, 0, 1, 128);
    gemm_tc<<<ggrid, 128>>>(W3, b3, nullptr, N, CDIM, 1, 0, 1);
    // layer 4 (no relu, write d_out)
    spmm_agg<<<N, 128>>>(nullptr, 0, 1, 128);
    gemm_tc<<<ggrid, 128>>>(W4, b4, out, N, CDIM, 1, -1, 0);
}